// round 7
// baseline (speedup 1.0000x reference)
#include <cuda_runtime.h>

typedef unsigned long long ull;
typedef long long ll;

#define THREADS 64
#define NWIN    8
#define WKEYS   128
#define TILE    64
#define FULLM   0xffffffffu
#define SCALE_F 0.125f

// smem (floats): lgt[32][65] | gw-region (pe_t[64][68] alias / gw[2][32][65]) | tot[64] | car[32]
#define LG_STRIDE 65
#define GW_STRIDE 65
#define PE_STRIDE 68
#define LGT_OFF   0
#define GW_OFF    (32 * LG_STRIDE)                 // 2080
#define GW_REGION (64 * PE_STRIDE)                 // 4352 (pe_t alias needs the max)
#define TOT_OFF   (GW_OFF + GW_REGION)             // 6432
#define CAR_OFF   (TOT_OFF + 64)                   // 6496
#define SMEM_FLOATS (CAR_OFF + 32)                 // 6528 -> 26112 B

__device__ __forceinline__ ull fma2(ull a, ull b, ull c) {
    ull d;
    asm("fma.rn.f32x2 %0, %1, %2, %3;" : "=l"(d) : "l"(a), "l"(b), "l"(c));
    return d;
}
__device__ __forceinline__ float hsum2(ull a) {
    unsigned lo, hi;
    asm("mov.b64 {%0, %1}, %2;" : "=r"(lo), "=r"(hi) : "l"(a));
    return __uint_as_float(lo) + __uint_as_float(hi);
}
__device__ __forceinline__ float sigm(float x) {
    return __fdividef(1.0f, 1.0f + __expf(-x));
}

__global__ void __launch_bounds__(THREADS, 8)
cope_kernel(const float* __restrict__ q, const float* __restrict__ kmat,
            const float* __restrict__ pos_emb, const int* __restrict__ flag_p,
            float* __restrict__ out)
{
    __shared__ float smem[SMEM_FLOATS];
    float* lgt  = smem + LGT_OFF;
    float* pe_t = smem + GW_OFF;     // phase 0/1 only; aliased by gw afterwards

    const int tid  = threadIdx.x;
    const int wid  = tid >> 5;
    const int lane = tid & 31;
    const ll  rowbase = (ll)blockIdx.x * 32;
    const int b = blockIdx.x >> 5;                   // 32 CTAs per batch
    const float* kbatch = kmat + (ll)b * 1024 * 64;

    // ---- Phase 0: pos_emb^T -> smem: pe_t[n][d] = pos_emb[d*64 + n]
    for (int i = tid; i < 4096; i += THREADS) {
        int d = i >> 6, n = i & 63;
        pe_t[n * PE_STRIDE + d] = pos_emb[i];
    }
    if (tid < 32) smem[CAR_OFF + tid] = 0.0f;
    __syncthreads();

    // ---- Phase 1: logits_int[row=lane][n], npos split across the 2 warps
    const int flag = *flag_p;
    ull qp[32];
    {
        const ulonglong2* bp =
            (const ulonglong2*)((flag ? q : kmat) + (rowbase + lane) * 64);
        #pragma unroll
        for (int j = 0; j < 16; ++j) { ulonglong2 v = bp[j]; qp[2*j] = v.x; qp[2*j+1] = v.y; }
    }
    {
        float* mylg = lgt + lane * LG_STRIDE;
        const int nb = wid * 32;
        for (int n0 = nb; n0 < nb + 32; n0 += 4) {
            const ulonglong2* p0 = (const ulonglong2*)(pe_t + (n0 + 0) * PE_STRIDE);
            const ulonglong2* p1 = (const ulonglong2*)(pe_t + (n0 + 1) * PE_STRIDE);
            const ulonglong2* p2 = (const ulonglong2*)(pe_t + (n0 + 2) * PE_STRIDE);
            const ulonglong2* p3 = (const ulonglong2*)(pe_t + (n0 + 3) * PE_STRIDE);
            ull a0 = 0, a1 = 0, a2 = 0, a3 = 0;
            #pragma unroll
            for (int i = 0; i < 16; ++i) {
                ulonglong2 v0 = p0[i], v1 = p1[i], v2 = p2[i], v3 = p3[i];
                a0 = fma2(qp[2*i], v0.x, a0); a0 = fma2(qp[2*i+1], v0.y, a0);
                a1 = fma2(qp[2*i], v1.x, a1); a1 = fma2(qp[2*i+1], v1.y, a1);
                a2 = fma2(qp[2*i], v2.x, a2); a2 = fma2(qp[2*i+1], v2.y, a2);
                a3 = fma2(qp[2*i], v3.x, a3); a3 = fma2(qp[2*i+1], v3.y, a3);
            }
            mylg[n0]     = hsum2(a0);
            mylg[n0 + 1] = hsum2(a1);
            mylg[n0 + 2] = hsum2(a2);
            mylg[n0 + 3] = hsum2(a3);
        }
        if (wid == 1) mylg[64] = 0.0f;     // guard: pos==63 -> w=0 path exact
    }
    if (!flag) {   // gates always use q
        const ulonglong2* bp = (const ulonglong2*)(q + (rowbase + lane) * 64);
        #pragma unroll
        for (int j = 0; j < 16; ++j) { ulonglong2 v = bp[j]; qp[2*j] = v.x; qp[2*j+1] = v.y; }
    }
    __syncthreads();   // lgt ready; pe_t region becomes gw

    // ---- Phase 2: window sweep (2 tiles/window, one per warp) + pass-2 emit
    float carry = 0.0f;                              // this thread's row carry (row = lane)
    float* myg = smem + GW_OFF + (wid * 32 + lane) * GW_STRIDE;

    for (int W = NWIN - 1; ; --W) {
        if (__syncthreads_and(carry >= 63.0f)) {
            // all rows saturated: fill keys [0, (W+1)*WKEYS) with logits[63], coalesced per row
            const int kend = (W + 1) * WKEYS;
            const int half = kend >> 1;
            for (int r = 0; r < 32; ++r) {
                float v = lgt[r * LG_STRIDE + 63];
                float4 vv = make_float4(v, v, v, v);
                float* dst = out + (rowbase + r) * 1024 + wid * half;
                for (int c = 4 * lane; c < half; c += 128)
                    __stcs((float4*)(dst + c), vv);
            }
            return;
        }

        const int kb = W * WKEYS + (1 - wid) * TILE;   // warp 0 takes the upper tile

        // sweep: local suffix sums over my 64-key tile (descending), early tail-exit
        float s = 0.0f;
        int g = 7;
        for (; g >= 0; --g) {
            if (__all_sync(FULLM, carry + s >= 63.0f)) break;  // conservative, exact under clamp
            const float* kp0 = kbatch + (ll)(kb + g * 8) * 64;
            ull acc[8];
            #pragma unroll
            for (int j = 0; j < 8; ++j) acc[j] = 0ull;
            #pragma unroll
            for (int i = 0; i < 16; ++i) {
                #pragma unroll
                for (int j = 0; j < 8; ++j) {
                    ulonglong2 v = *(const ulonglong2*)(kp0 + j * 64 + i * 4);
                    acc[j] = fma2(qp[2*i],     v.x, acc[j]);
                    acc[j] = fma2(qp[2*i + 1], v.y, acc[j]);
                }
            }
            float gg[8];
            #pragma unroll
            for (int j = 0; j < 8; ++j) gg[j] = sigm(hsum2(acc[j]) * SCALE_F);
            #pragma unroll
            for (int j = 7; j >= 0; --j) { s += gg[j]; myg[g * 8 + j] = s; }
        }
        if (g >= 0) {                                    // tail-exit: sentinel suffixes
            const int cnt = (g + 1) * 8;
            for (int jj = 0; jj < cnt; ++jj) myg[jj] = 1e9f;
        }
        smem[TOT_OFF + wid * 32 + lane] = s;
        __syncthreads();

        // pass 2: exact carries + interpolation, coalesced float2 stores
        for (int r = 0; r < 32; ++r) {
            float cin = smem[CAR_OFF + r] + (wid ? smem[TOT_OFF + r] : 0.0f);
            const float* gr = smem + GW_OFF + (wid * 32 + r) * GW_STRIDE;
            const float* lr = lgt + r * LG_STRIDE;
            float sA = gr[2 * lane], sB = gr[2 * lane + 1];
            float pA = fminf(cin + sA, 63.0f);
            float pB = fminf(cin + sB, 63.0f);
            float fA = floorf(pA), fB = floorf(pB);
            int   iA = (int)fA,    iB = (int)fB;
            float wA = pA - fA,    wB = pB - fB;
            float2 o;
            o.x = lr[iA + 1] * wA + lr[iA] * (1.0f - wA);
            o.y = lr[iB + 1] * wB + lr[iB] * (1.0f - wB);
            __stcs((float2*)(out + (rowbase + r) * 1024 + kb) + lane, o);
        }

        carry += smem[TOT_OFF + lane] + smem[TOT_OFF + 32 + lane];
        __syncthreads();                       // pass-2 reads done before carry table update
        if (tid < 32) smem[CAR_OFF + tid] = carry;
        if (W == 0) return;
    }
}

extern "C" void kernel_launch(void* const* d_in, const int* in_sizes, int n_in,
                              void* d_out, int out_size) {
    const float* q    = (const float*)d_in[0];
    const float* k    = (const float*)d_in[1];
    // d_in[2] = v (unused in mode 0)
    const float* pe   = (const float*)d_in[3];
    // d_in[4] = w_k (unused)
    const int*   flag = (const int*)d_in[5];
    float* out = (float*)d_out;

    const int grid = (32 * 1024) / 32;   // 1024 CTAs, 32 rows each
    cope_kernel<<<grid, THREADS>>>(q, k, pe, flag, out);
}

// round 8
// speedup vs baseline: 1.1121x; 1.1121x over previous
#include <cuda_runtime.h>

typedef unsigned long long ull;

#define THREADS 256
#define SCALE_F 0.125f
#define FULLM   0xffffffffu
#define PAD     66

// smem float offsets
#define QSM 0
#define KSM (64 * PAD)          // 4224
#define GSM (2 * 64 * PAD)      // 8448
#define LGT (3 * 64 * PAD)      // 12672
#define CAR (4 * 64 * PAD)      // 16896
#define SMEM_FLOATS (CAR + 64)
#define SMEM_BYTES  (SMEM_FLOATS * 4)   // 67840 B -> 3 CTAs/SM

__device__ __forceinline__ ull fma2(ull a, ull b, ull c) {
    ull d;
    asm("fma.rn.f32x2 %0, %1, %2, %3;" : "=l"(d) : "l"(a), "l"(b), "l"(c));
    return d;
}
__device__ __forceinline__ float hsum2(ull a) {
    unsigned lo, hi;
    asm("mov.b64 {%0, %1}, %2;" : "=r"(lo), "=r"(hi) : "l"(a));
    return __uint_as_float(lo) + __uint_as_float(hi);
}
__device__ __forceinline__ float sigm(float x) {
    return __fdividef(1.0f, 1.0f + __expf(-x));
}

// cooperative load of a row-major 64x64 gmem tile into smem [64][PAD]
__device__ __forceinline__ void load64(const float* __restrict__ src, float* dst, int tid) {
    #pragma unroll
    for (int r = 0; r < 4; ++r) {
        int f   = tid + r * THREADS;
        int row = f >> 4;
        int dp  = (f & 15) * 4;
        float4 v = *(const float4*)(src + row * 64 + dp);
        float* p = dst + row * PAD + dp;
        *(float2*)p       = make_float2(v.x, v.y);
        *(float2*)(p + 2) = make_float2(v.z, v.w);
    }
}

// 64x64x64 register-tiled GEMM: dst[row][key] = qs[row]·ks[key]  (+sigmoid if GATE)
// 8 warps: warp = (row-half, key-quarter); thread frag = 4 rows x 4 keys
template <bool GATE>
__device__ __forceinline__ void gemm64(const float* qs, const float* ks, float* dst,
                                       int lane, int w)
{
    const int row0 = (w >> 2) * 32 + (lane >> 2) * 4;
    const int key0 = (w & 3) * 16 + (lane & 3) * 4;
    ull acc[4][4];
    #pragma unroll
    for (int i = 0; i < 4; ++i)
        #pragma unroll
        for (int j = 0; j < 4; ++j) acc[i][j] = 0ull;

    #pragma unroll 8
    for (int d = 0; d < 64; d += 2) {
        ull qv[4], kv[4];
        #pragma unroll
        for (int i = 0; i < 4; ++i) qv[i] = *(const ull*)(qs + (row0 + i) * PAD + d);
        #pragma unroll
        for (int j = 0; j < 4; ++j) kv[j] = *(const ull*)(ks + (key0 + j) * PAD + d);
        #pragma unroll
        for (int i = 0; i < 4; ++i)
            #pragma unroll
            for (int j = 0; j < 4; ++j)
                acc[i][j] = fma2(qv[i], kv[j], acc[i][j]);
    }
    #pragma unroll
    for (int i = 0; i < 4; ++i) {
        float v0 = hsum2(acc[i][0]), v1 = hsum2(acc[i][1]);
        float v2 = hsum2(acc[i][2]), v3 = hsum2(acc[i][3]);
        if (GATE) {
            v0 = sigm(v0 * SCALE_F); v1 = sigm(v1 * SCALE_F);
            v2 = sigm(v2 * SCALE_F); v3 = sigm(v3 * SCALE_F);
        }
        float* p = dst + (row0 + i) * PAD + key0;
        *(float2*)p       = make_float2(v0, v1);
        *(float2*)(p + 2) = make_float2(v2, v3);
    }
}

__global__ void __launch_bounds__(THREADS, 3)
cope_kernel(const float* __restrict__ q, const float* __restrict__ kmat,
            const float* __restrict__ pe, const int* __restrict__ flagp,
            float* __restrict__ out)
{
    extern __shared__ float sm[];
    float* qsm = sm + QSM;
    float* ksm = sm + KSM;
    float* gsm = sm + GSM;
    float* lgt = sm + LGT;
    float* car = sm + CAR;

    const int tid  = threadIdx.x;
    const int w    = tid >> 5;
    const int lane = tid & 31;
    const int b    = blockIdx.x >> 4;
    const int rb   = blockIdx.x & 15;
    const int rowg0 = b * 1024 + rb * 64;            // global query-row base
    const float* kb = kmat + b * 1024 * 64;
    const int flag = *flagp;

    // ---- loaders: pe^T -> ksm, base rows -> qsm, carry = 0
    for (int i = tid; i < 4096; i += THREADS) {      // pe[d][n] -> ksm[n][d]
        int d = i >> 6, n = i & 63;
        ksm[n * PAD + d] = pe[i];
    }
    load64((flag ? q : kmat) + rowg0 * 64, qsm, tid);
    if (tid < 64) car[tid] = 0.0f;
    __syncthreads();

    // ---- logits_int table: lgt[row][n] = base[row]·pe[:,n]
    gemm64<false>(qsm, ksm, lgt, lane, w);
    __syncthreads();
    if (tid < 64) lgt[tid * PAD + 64] = 0.0f;        // guard: pos==63 -> w=0 exact
    if (!flag) load64(q + rowg0 * 64, qsm, tid);     // gates always use q
    // ordering to first gemm read is provided by the first vote's barrier

    // ---- tile loop: gate GEMM -> scan -> vote, descending keys
    int kend = 0;
    for (int T = 15; T >= 0; --T) {
        bool sat = car[tid & 63] >= 63.0f;
        if (__syncthreads_and(sat)) { kend = (T + 1) * 64; break; }

        load64(kb + T * 64 * 64, ksm, tid);
        __syncthreads();
        gemm64<true>(qsm, ksm, gsm, lane, w);        // sigmoid gates into gsm
        __syncthreads();

        // scan: warp w owns rows w*8..w*8+7; two 32-key chunks, high first
        float cl[8];
        #pragma unroll
        for (int rr = 0; rr < 8; ++rr) cl[rr] = car[w * 8 + rr];

        #pragma unroll
        for (int c = 1; c >= 0; --c) {
            float s[8];
            #pragma unroll
            for (int rr = 0; rr < 8; ++rr)
                s[rr] = gsm[(w * 8 + rr) * PAD + c * 32 + lane];
            #pragma unroll
            for (int off = 1; off < 32; off <<= 1) {
                #pragma unroll
                for (int rr = 0; rr < 8; ++rr) {
                    float u = __shfl_down_sync(FULLM, s[rr], off);
                    if (lane + off < 32) s[rr] += u;
                }
            }
            #pragma unroll
            for (int rr = 0; rr < 8; ++rr) {
                float pos = fminf(cl[rr] + s[rr], 63.0f);
                float pf  = floorf(pos);
                int   ip  = (int)pf;
                float wt  = pos - pf;
                const float* lr = lgt + (w * 8 + rr) * PAD;
                float val = lr[ip + 1] * wt + lr[ip] * (1.0f - wt);
                __stcs(out + (rowg0 + w * 8 + rr) * 1024 + T * 64 + c * 32 + lane, val);
            }
            #pragma unroll
            for (int rr = 0; rr < 8; ++rr)
                cl[rr] += __shfl_sync(FULLM, s[rr], 0);
        }
        if (lane == 0) {
            #pragma unroll
            for (int rr = 0; rr < 8; ++rr) car[w * 8 + rr] = cl[rr];
        }
        // next vote's barrier orders car / gsm / ksm reuse
    }

    // ---- saturated bulk fill: keys [0, kend) = logits_int[row][63]
    if (kend > 0) {
        #pragma unroll
        for (int rr = 0; rr < 8; ++rr) {
            int r = w * 8 + rr;
            float v = lgt[r * PAD + 63];
            float4 vv = make_float4(v, v, v, v);
            float* dst = out + (rowg0 + r) * 1024;
            for (int c = 4 * lane; c < kend; c += 128)
                __stcs((float4*)(dst + c), vv);
        }
    }
}

extern "C" void kernel_launch(void* const* d_in, const int* in_sizes, int n_in,
                              void* d_out, int out_size) {
    const float* q    = (const float*)d_in[0];
    const float* k    = (const float*)d_in[1];
    // d_in[2] = v (unused in mode 0)
    const float* pe   = (const float*)d_in[3];
    // d_in[4] = w_k (unused)
    const int*   flag = (const int*)d_in[5];
    float* out = (float*)d_out;

    cudaFuncSetAttribute(cope_kernel, cudaFuncAttributeMaxDynamicSharedMemorySize, SMEM_BYTES);
    const int grid = 32 * 16;   // 512 CTAs: 32 batches x 16 row-blocks of 64
    cope_kernel<<<grid, THREADS, SMEM_BYTES>>>(q, k, pe, flag, out);
}